// round 5
// baseline (speedup 1.0000x reference)
#include <cuda_runtime.h>
#include <cstddef>

#define IMH 1024
#define IMW 1024
#define SFRAMES 8
#define NB 4
#define TR 32            // tile rows (output)
#define TC 128           // tile cols
#define NTHREADS 512
#define NW (NTHREADS / 32)       // 16 warps
#define GH (TR + 8)              // 40 rows incl vertical halo
#define RBW 136                  // per-warp row buffer width (128 + 8 halo)

// smem layout (floats): sHA[GH*TC] | sHB[GH*TC] | sRow[NW*RBW]
#define SMEM_FLOATS (2 * GH * TC + NW * RBW)
#define SMEM_BYTES  (SMEM_FLOATS * 4)

// 128 MB scratch for per-frame laplacian maps
__device__ float g_lap[(size_t)NB * SFRAMES * IMH * IMW];

__device__ __forceinline__ int reflect101(int i, int n) {
    if (i < 0) i = -i;
    if (i >= n) i = 2 * n - 2 - i;
    return i;
}

// ============================================================================
// Kernel A: per-frame laplacian-of-gaussian (composed 9x9, separable) -> g_lap
// ============================================================================
extern "C" __global__ void __launch_bounds__(NTHREADS, 3)
lap_kernel(const float* __restrict__ x)
{
    extern __shared__ float smem[];
    float* sHA  = smem;                    // horizontal A-filtered, GH x TC
    float* sHB  = smem + GH * TC;          // horizontal B-filtered, GH x TC
    float* sRow = smem + 2 * GH * TC;      // per-warp gray row buffers

    const int tid  = threadIdx.x;
    const int lane = tid & 31;
    const int warp = tid >> 5;
    const int z    = blockIdx.z;           // b * SFRAMES + s
    const int hr0  = blockIdx.y * TR;
    const int wc0  = blockIdx.x * TC;
    const size_t HW = (size_t)IMH * IMW;
    const float ONE3 = 0.33333334f;

    const float* __restrict__ xf = x + (size_t)z * 3 * HW;
    float* rowbuf = sRow + warp * RBW;

    // ==== Phase 1: gray + horizontal 9-tap A/B, per-warp ====
    for (int r = warp; r < GH; r += NW) {
        const int gr = reflect101(hr0 - 4 + r, IMH);
        const float* __restrict__ p0 = xf + (size_t)gr * IMW;
        const int c0 = wc0 + lane * 4;

        float4 ra = *reinterpret_cast<const float4*>(p0 + c0);
        float4 rb = *reinterpret_cast<const float4*>(p0 + HW + c0);
        float4 rc = *reinterpret_cast<const float4*>(p0 + 2 * HW + c0);
        float4 g4;
        g4.x = (ra.x + rb.x + rc.x) * ONE3;
        g4.y = (ra.y + rb.y + rc.y) * ONE3;
        g4.z = (ra.z + rb.z + rc.z) * ONE3;
        g4.w = (ra.w + rb.w + rc.w) * ONE3;
        *reinterpret_cast<float4*>(rowbuf + 4 + lane * 4) = g4;

        if (lane == 0) {
            if (wc0 >= 4) {
                float4 ha = *reinterpret_cast<const float4*>(p0 + wc0 - 4);
                float4 hb = *reinterpret_cast<const float4*>(p0 + HW + wc0 - 4);
                float4 hc = *reinterpret_cast<const float4*>(p0 + 2 * HW + wc0 - 4);
                rowbuf[0] = (ha.x + hb.x + hc.x) * ONE3;
                rowbuf[1] = (ha.y + hb.y + hc.y) * ONE3;
                rowbuf[2] = (ha.z + hb.z + hc.z) * ONE3;
                rowbuf[3] = (ha.w + hb.w + hc.w) * ONE3;
            } else {
#pragma unroll
                for (int j = 0; j < 4; j++) {
                    int gc = reflect101(wc0 - 4 + j, IMW);
                    rowbuf[j] = (__ldg(p0 + gc) + __ldg(p0 + HW + gc)
                                 + __ldg(p0 + 2 * HW + gc)) * ONE3;
                }
            }
        } else if (lane == 31) {
            int cR = wc0 + TC;
            if (cR + 3 < IMW) {
                float4 ha = *reinterpret_cast<const float4*>(p0 + cR);
                float4 hb = *reinterpret_cast<const float4*>(p0 + HW + cR);
                float4 hc = *reinterpret_cast<const float4*>(p0 + 2 * HW + cR);
                rowbuf[132] = (ha.x + hb.x + hc.x) * ONE3;
                rowbuf[133] = (ha.y + hb.y + hc.y) * ONE3;
                rowbuf[134] = (ha.z + hb.z + hc.z) * ONE3;
                rowbuf[135] = (ha.w + hb.w + hc.w) * ONE3;
            } else {
#pragma unroll
                for (int j = 0; j < 4; j++) {
                    int gc = reflect101(cR + j, IMW);
                    rowbuf[132 + j] = (__ldg(p0 + gc) + __ldg(p0 + HW + gc)
                                       + __ldg(p0 + 2 * HW + gc)) * ONE3;
                }
            }
        }
        __syncwarp();

        float w[12];
#pragma unroll
        for (int j = 0; j < 12; j += 4)
            *reinterpret_cast<float4*>(&w[j]) =
                *reinterpret_cast<const float4*>(rowbuf + lane * 4 + j);

        float4 hA4, hB4;
#pragma unroll
        for (int o = 0; o < 4; o++) {
            float p1 = w[o + 3] + w[o + 5];
            float p2 = w[o + 2] + w[o + 6];
            float p3 = w[o + 1] + w[o + 7];
            float p4 = w[o + 0] + w[o + 8];
            float ctr = w[o + 4];
            float tA =  4.375f * ctr + 3.5f  * p1 + 1.75f * p2 + 0.5f  * p3 + 0.0625f * p4;
            float tB = -0.625f * ctr - 0.25f * p1 + 0.25f * p2 + 0.25f * p3 + 0.0625f * p4;
            (&hA4.x)[o] = tA;
            (&hB4.x)[o] = tB;
        }
        *reinterpret_cast<float4*>(&sHA[r * TC + lane * 4]) = hA4;
        *reinterpret_cast<float4*>(&sHB[r * TC + lane * 4]) = hB4;
        __syncwarp();
    }
    __syncthreads();

    // ==== Phase 2: vertical 9-tap (B on hA + A on hB) -> g_lap ====
    const float wAv[9] = {0.0625f, 0.5f, 1.75f, 3.5f, 4.375f, 3.5f, 1.75f, 0.5f, 0.0625f};
    const float wBv[9] = {0.0625f, 0.25f, 0.25f, -0.25f, -0.625f, -0.25f, 0.25f, 0.25f, 0.0625f};
#pragma unroll
    for (int it = 0; it < 2; it++) {
        const int t  = tid + it * NTHREADS;     // < 1024 exactly
        const int r  = t >> 5;
        const int cg = t & 31;
        const int base = r * TC + cg * 4;
        float acc0 = 0.f, acc1 = 0.f, acc2 = 0.f, acc3 = 0.f;
#pragma unroll
        for (int j = 0; j < 9; j++) {
            float4 ha = *reinterpret_cast<const float4*>(&sHA[base + j * TC]);
            float4 hb = *reinterpret_cast<const float4*>(&sHB[base + j * TC]);
            acc0 += wBv[j] * ha.x + wAv[j] * hb.x;
            acc1 += wBv[j] * ha.y + wAv[j] * hb.y;
            acc2 += wBv[j] * ha.z + wAv[j] * hb.z;
            acc3 += wBv[j] * ha.w + wAv[j] * hb.w;
        }
        const size_t off = (size_t)z * HW + (size_t)(hr0 + r) * IMW + wc0 + cg * 4;
        *reinterpret_cast<float4*>(&g_lap[off]) = make_float4(acc0, acc1, acc2, acc3);
    }
}

// ============================================================================
// Kernel B: per-pixel argmax over 8 frames + RGB gather
// ============================================================================
#define BTHREADS 256
#define PXPT 4    // pixels per thread (one float4)

extern "C" __global__ void __launch_bounds__(BTHREADS)
merge_kernel(const float* __restrict__ x, float* __restrict__ out)
{
    const int b = blockIdx.y;
    const size_t HW = (size_t)IMH * IMW;
    const size_t p = ((size_t)blockIdx.x * BTHREADS + threadIdx.x) * PXPT;

    const float* __restrict__ lapb = g_lap + (size_t)b * SFRAMES * HW;

    float best0 = -3.0e38f, best1 = -3.0e38f, best2 = -3.0e38f, best3 = -3.0e38f;
    unsigned i0 = 0, i1 = 0, i2 = 0, i3 = 0;
#pragma unroll
    for (int s = 0; s < SFRAMES; s++) {
        float4 v = __ldg(reinterpret_cast<const float4*>(lapb + s * HW + p));
        if (v.x > best0) { best0 = v.x; i0 = s; }
        if (v.y > best1) { best1 = v.y; i1 = s; }
        if (v.z > best2) { best2 = v.z; i2 = s; }
        if (v.w > best3) { best3 = v.w; i3 = s; }
    }

    const float* __restrict__ xb = x + (size_t)b * SFRAMES * 3 * HW;
    unsigned idx[4] = {i0, i1, i2, i3};
    float R[4], G[4], B[4];
#pragma unroll
    for (int o = 0; o < 4; o++) {
        const float* __restrict__ xw = xb + (size_t)idx[o] * 3 * HW + p + o;
        R[o] = __ldg(xw);
        G[o] = __ldg(xw + HW);
        B[o] = __ldg(xw + 2 * HW);
    }

    float* __restrict__ ob = out + (size_t)b * 3 * HW + p;
    *reinterpret_cast<float4*>(ob)          = make_float4(R[0], R[1], R[2], R[3]);
    *reinterpret_cast<float4*>(ob + HW)     = make_float4(G[0], G[1], G[2], G[3]);
    *reinterpret_cast<float4*>(ob + 2 * HW) = make_float4(B[0], B[1], B[2], B[3]);
}

// ============================================================================
extern "C" void kernel_launch(void* const* d_in, const int* in_sizes, int n_in,
                              void* d_out, int out_size)
{
    const float* x = (const float*)d_in[0];
    float* out = (float*)d_out;

    cudaFuncSetAttribute(lap_kernel,
                         cudaFuncAttributeMaxDynamicSharedMemorySize, SMEM_BYTES);

    dim3 gridA(IMW / TC, IMH / TR, NB * SFRAMES);
    lap_kernel<<<gridA, NTHREADS, SMEM_BYTES>>>(x);

    dim3 gridB((IMH * IMW) / (BTHREADS * PXPT), NB);
    merge_kernel<<<gridB, BTHREADS>>>(x, out);
}

// round 6
// speedup vs baseline: 1.0361x; 1.0361x over previous
#include <cuda_runtime.h>
#include <cstddef>

#define IMH 1024
#define IMW 1024
#define SFRAMES 8
#define NB 4
#define TR 32            // tile rows (output)
#define TC 128           // tile cols
#define NTHREADS 512
#define GH (TR + 8)      // 40 rows incl vertical halo
#define GWF 136          // gray tile width incl horizontal halo (floats)
#define NT4 (GH * 34)    // 1360 float4 load tasks (34 float4 per row)

// smem layout (floats): sG[GH*GWF] | sHA[GH*TC] | sHB[GH*TC]
#define SMEM_FLOATS (GH * GWF + 2 * GH * TC)
#define SMEM_BYTES  (SMEM_FLOATS * 4)

// 128 MB scratch for per-frame laplacian maps
__device__ float g_lap[(size_t)NB * SFRAMES * IMH * IMW];

__device__ __forceinline__ int reflect101(int i, int n) {
    if (i < 0) i = -i;
    if (i >= n) i = 2 * n - 2 - i;
    return i;
}

// ============================================================================
// Kernel A: per-frame laplacian-of-gaussian (composed 9x9, separable) -> g_lap
// ============================================================================
extern "C" __global__ void __launch_bounds__(NTHREADS, 3)
lap_kernel(const float* __restrict__ x)
{
    extern __shared__ float smem[];
    float* sG  = smem;                      // GH x GWF gray (+halo)
    float* sHA = smem + GH * GWF;           // GH x TC horizontal A-filtered
    float* sHB = sHA + GH * TC;             // GH x TC horizontal B-filtered

    const int tid = threadIdx.x;
    const int z   = blockIdx.z;             // b * SFRAMES + s
    const int hr0 = blockIdx.y * TR;
    const int wc0 = blockIdx.x * TC;
    const size_t HW = (size_t)IMH * IMW;
    const float ONE3 = 0.33333334f;

    const float* __restrict__ xf = x + (size_t)z * 3 * HW;

    // ==== Phase 1a: gray tile load (flat, high-MLP) ====
    if (blockIdx.x != 0 && (int)blockIdx.x != (int)gridDim.x - 1) {
        // interior: all columns wc0-4 .. wc0+131 in range, float4-aligned
#pragma unroll
        for (int k = 0; k < 3; k++) {
            const int t = tid + k * NTHREADS;
            if (t < NT4) {
                const int r  = t / 34;
                const int c4 = t - r * 34;
                const int gr = reflect101(hr0 - 4 + r, IMH);
                const float* __restrict__ p = xf + (size_t)gr * IMW + (wc0 - 4 + c4 * 4);
                float4 a = *reinterpret_cast<const float4*>(p);
                float4 bq = *reinterpret_cast<const float4*>(p + HW);
                float4 c = *reinterpret_cast<const float4*>(p + 2 * HW);
                float4 g;
                g.x = (a.x + bq.x + c.x) * ONE3;
                g.y = (a.y + bq.y + c.y) * ONE3;
                g.z = (a.z + bq.z + c.z) * ONE3;
                g.w = (a.w + bq.w + c.w) * ONE3;
                *reinterpret_cast<float4*>(&sG[r * GWF + c4 * 4]) = g;
            }
        }
    } else {
        // edge blocks: scalar path with full reflect
        for (int i = tid; i < GH * GWF; i += NTHREADS) {
            const int r = i / GWF;
            const int c = i - r * GWF;
            const int gr = reflect101(hr0 - 4 + r, IMH);
            const int gc = reflect101(wc0 - 4 + c, IMW);
            const float* __restrict__ p = xf + (size_t)gr * IMW + gc;
            sG[i] = (__ldg(p) + __ldg(p + HW) + __ldg(p + 2 * HW)) * ONE3;
        }
    }
    __syncthreads();

    // ==== Phase 1b: horizontal 9-tap A/B from sG -> sHA/sHB ====
#pragma unroll
    for (int k = 0; k < 3; k++) {
        const int t = tid + k * NTHREADS;   // GH*32 = 1280 tasks
        if (t < GH * 32) {
            const int r  = t >> 5;
            const int cg = t & 31;
            float w[12];
#pragma unroll
            for (int j = 0; j < 12; j += 4)
                *reinterpret_cast<float4*>(&w[j]) =
                    *reinterpret_cast<const float4*>(&sG[r * GWF + cg * 4 + j]);
            float4 hA4, hB4;
#pragma unroll
            for (int o = 0; o < 4; o++) {
                float p1 = w[o + 3] + w[o + 5];
                float p2 = w[o + 2] + w[o + 6];
                float p3 = w[o + 1] + w[o + 7];
                float p4 = w[o + 0] + w[o + 8];
                float ctr = w[o + 4];
                (&hA4.x)[o] =  4.375f * ctr + 3.5f  * p1 + 1.75f * p2 + 0.5f  * p3 + 0.0625f * p4;
                (&hB4.x)[o] = -0.625f * ctr - 0.25f * p1 + 0.25f * p2 + 0.25f * p3 + 0.0625f * p4;
            }
            *reinterpret_cast<float4*>(&sHA[r * TC + cg * 4]) = hA4;
            *reinterpret_cast<float4*>(&sHB[r * TC + cg * 4]) = hB4;
        }
    }
    __syncthreads();

    // ==== Phase 2: vertical 9-tap (B on hA + A on hB) -> g_lap ====
    const float wAv[9] = {0.0625f, 0.5f, 1.75f, 3.5f, 4.375f, 3.5f, 1.75f, 0.5f, 0.0625f};
    const float wBv[9] = {0.0625f, 0.25f, 0.25f, -0.25f, -0.625f, -0.25f, 0.25f, 0.25f, 0.0625f};
#pragma unroll
    for (int it = 0; it < 2; it++) {
        const int t  = tid + it * NTHREADS;     // TR*32 = 1024 tasks exactly
        const int r  = t >> 5;
        const int cg = t & 31;
        const int base = r * TC + cg * 4;
        float acc0 = 0.f, acc1 = 0.f, acc2 = 0.f, acc3 = 0.f;
#pragma unroll
        for (int j = 0; j < 9; j++) {
            float4 ha = *reinterpret_cast<const float4*>(&sHA[base + j * TC]);
            float4 hb = *reinterpret_cast<const float4*>(&sHB[base + j * TC]);
            acc0 += wBv[j] * ha.x + wAv[j] * hb.x;
            acc1 += wBv[j] * ha.y + wAv[j] * hb.y;
            acc2 += wBv[j] * ha.z + wAv[j] * hb.z;
            acc3 += wBv[j] * ha.w + wAv[j] * hb.w;
        }
        const size_t off = (size_t)z * HW + (size_t)(hr0 + r) * IMW + wc0 + cg * 4;
        *reinterpret_cast<float4*>(&g_lap[off]) = make_float4(acc0, acc1, acc2, acc3);
    }
}

// ============================================================================
// Kernel B: per-pixel argmax over 8 frames + RGB gather (84us @ 84% DRAM -- keep)
// ============================================================================
#define BTHREADS 256
#define PXPT 4    // pixels per thread (one float4)

extern "C" __global__ void __launch_bounds__(BTHREADS)
merge_kernel(const float* __restrict__ x, float* __restrict__ out)
{
    const int b = blockIdx.y;
    const size_t HW = (size_t)IMH * IMW;
    const size_t p = ((size_t)blockIdx.x * BTHREADS + threadIdx.x) * PXPT;

    const float* __restrict__ lapb = g_lap + (size_t)b * SFRAMES * HW;

    float best0 = -3.0e38f, best1 = -3.0e38f, best2 = -3.0e38f, best3 = -3.0e38f;
    unsigned i0 = 0, i1 = 0, i2 = 0, i3 = 0;
#pragma unroll
    for (int s = 0; s < SFRAMES; s++) {
        float4 v = __ldg(reinterpret_cast<const float4*>(lapb + s * HW + p));
        if (v.x > best0) { best0 = v.x; i0 = s; }
        if (v.y > best1) { best1 = v.y; i1 = s; }
        if (v.z > best2) { best2 = v.z; i2 = s; }
        if (v.w > best3) { best3 = v.w; i3 = s; }
    }

    const float* __restrict__ xb = x + (size_t)b * SFRAMES * 3 * HW;
    unsigned idx[4] = {i0, i1, i2, i3};
    float R[4], G[4], B[4];
#pragma unroll
    for (int o = 0; o < 4; o++) {
        const float* __restrict__ xw = xb + (size_t)idx[o] * 3 * HW + p + o;
        R[o] = __ldg(xw);
        G[o] = __ldg(xw + HW);
        B[o] = __ldg(xw + 2 * HW);
    }

    float* __restrict__ ob = out + (size_t)b * 3 * HW + p;
    *reinterpret_cast<float4*>(ob)          = make_float4(R[0], R[1], R[2], R[3]);
    *reinterpret_cast<float4*>(ob + HW)     = make_float4(G[0], G[1], G[2], G[3]);
    *reinterpret_cast<float4*>(ob + 2 * HW) = make_float4(B[0], B[1], B[2], B[3]);
}

// ============================================================================
extern "C" void kernel_launch(void* const* d_in, const int* in_sizes, int n_in,
                              void* d_out, int out_size)
{
    const float* x = (const float*)d_in[0];
    float* out = (float*)d_out;

    cudaFuncSetAttribute(lap_kernel,
                         cudaFuncAttributeMaxDynamicSharedMemorySize, SMEM_BYTES);

    dim3 gridA(IMW / TC, IMH / TR, NB * SFRAMES);
    lap_kernel<<<gridA, NTHREADS, SMEM_BYTES>>>(x);

    dim3 gridB((IMH * IMW) / (BTHREADS * PXPT), NB);
    merge_kernel<<<gridB, BTHREADS>>>(x, out);
}